// round 1
// baseline (speedup 1.0000x reference)
#include <cuda_runtime.h>

#define N 4096

// Scratch ping-pong buffer (allocation-free rule: __device__ global).
__device__ float g_buf[(size_t)N * N];

__global__ void init_kernel(const float* __restrict__ X,
                            const float* __restrict__ Y,
                            float* __restrict__ out) {
    int i = blockIdx.x * blockDim.x + threadIdx.x;
    float dx = X[i] - 0.5f;
    float dy = Y[i] - 0.5f;
    out[i] = __expf(-50.0f * (dx * dx + dy * dy));
}

__global__ void step_kernel(const float* __restrict__ in,
                            float* __restrict__ out) {
    int x = blockIdx.x * blockDim.x + threadIdx.x;
    int y = blockIdx.y * blockDim.y + threadIdx.y;
    float v = 0.0f;
    if (x > 0 && x < N - 1 && y > 0 && y < N - 1) {
        const float* row = in + (size_t)y * N + x;
        v = 0.25f * (row[-1] + row[1] + row[-N] + row[N]);
    }
    out[(size_t)y * N + x] = v;
}

extern "C" void kernel_launch(void* const* d_in, const int* in_sizes, int n_in,
                              void* d_out, int out_size) {
    const float* X = (const float*)d_in[0];
    const float* Y = (const float*)d_in[1];
    float* A = (float*)d_out;   // ping buffer (also final output)
    float* B;
    cudaGetSymbolAddress((void**)&B, g_buf);

    // init: x0 -> A
    {
        int threads = 256;
        int blocks = (N * N) / threads;
        init_kernel<<<blocks, threads>>>(X, Y, A);
    }

    // 100 Jacobi sweeps, ping-pong A <-> B. 100 even -> final lands in A (=d_out).
    dim3 block(128, 2);
    dim3 grid(N / block.x, N / block.y);
    for (int t = 0; t < 100; t++) {
        const float* src = (t % 2 == 0) ? A : B;
        float*       dst = (t % 2 == 0) ? B : A;
        step_kernel<<<grid, block>>>(src, dst);
    }
}

// round 2
// speedup vs baseline: 3.4335x; 3.4335x over previous
#include <cuda_runtime.h>

#define N    4096
#define K    10          // fused Jacobi steps per pass
#define TX   108         // output tile edge (TX + 2K = 128)
#define BW   128         // smem buffer edge
#define NBLK 38          // ceil(4096 / 108)
#define NTH  512

// Scratch ping-pong buffer (allocation-free rule: __device__ global).
__device__ float g_buf[(size_t)N * N];

__global__ void init_kernel(const float* __restrict__ X,
                            const float* __restrict__ Y,
                            float* __restrict__ out) {
    int i = blockIdx.x * blockDim.x + threadIdx.x;
    float dx = X[i] - 0.5f;
    float dy = Y[i] - 0.5f;
    out[i] = __expf(-50.0f * (dx * dx + dy * dy));
}

__global__ __launch_bounds__(NTH, 1)
void jacobi_pass(const float* __restrict__ in, float* __restrict__ out) {
    extern __shared__ float smem[];
    float* b0 = smem;
    float* b1 = smem + BW * BW;

    const int tid = threadIdx.x;
    const int gx0 = blockIdx.x * TX - K;
    const int gy0 = blockIdx.y * TX - K;

    // ---- load 128x128 tile (zero-fill outside domain) ----
    for (int i = tid; i < BW * BW; i += NTH) {
        int x = i & (BW - 1);
        int y = i >> 7;
        int gx = gx0 + x, gy = gy0 + y;
        float v = 0.0f;
        if (gx >= 0 && gx < N && gy >= 0 && gy < N)
            v = in[(size_t)gy * N + gx];
        b0[i] = v;
    }
    __syncthreads();

    const int lane = tid & 31;
    const int warp = tid >> 5;          // 0..15
    const int x4   = lane * 4;          // float4 column, covers x 0..127

    // per-thread domain-interior masks for the 4 x positions
    const int gxb = gx0 + x4;
    const bool xin0 = (gxb + 0 >= 1) && (gxb + 0 <= N - 2);
    const bool xin1 = (gxb + 1 >= 1) && (gxb + 1 <= N - 2);
    const bool xin2 = (gxb + 2 >= 1) && (gxb + 2 <= N - 2);
    const bool xin3 = (gxb + 3 >= 1) && (gxb + 3 <= N - 2);

    // contiguous row chunk per warp: rows 1..126 split into 16 chunks of 8
    const int y_beg = 1 + warp * 8;
    const int y_end = min(y_beg + 8, BW - 1);   // exclusive

    // ---- K fused Jacobi steps in smem (ping-pong b0 <-> b1) ----
    for (int s = 0; s < K; s++) {
        const float* src = (s & 1) ? b1 : b0;
        float*       dst = (s & 1) ? b0 : b1;

        float4 up  = *(const float4*)(src + (y_beg - 1) * BW + x4);
        float4 cur = *(const float4*)(src + (y_beg    ) * BW + x4);

        for (int y = y_beg; y < y_end; y++) {
            float4 dn = *(const float4*)(src + (y + 1) * BW + x4);
            // lane-edge scalars via warp shuffle (edge lanes get garbage;
            // it stays inside the halo, <= 1 cell/step inward)
            float lf = __shfl_up_sync(0xffffffffu, cur.w, 1);
            float rt = __shfl_down_sync(0xffffffffu, cur.x, 1);

            int  gy  = gy0 + y;
            bool yin = (gy >= 1) && (gy <= N - 2);

            float4 o;
            o.x = (yin && xin0) ? 0.25f * (lf    + cur.y + up.x + dn.x) : 0.0f;
            o.y = (yin && xin1) ? 0.25f * (cur.x + cur.z + up.y + dn.y) : 0.0f;
            o.z = (yin && xin2) ? 0.25f * (cur.y + cur.w + up.z + dn.z) : 0.0f;
            o.w = (yin && xin3) ? 0.25f * (cur.z + rt    + up.w + dn.w) : 0.0f;
            *(float4*)(dst + y * BW + x4) = o;

            up = cur; cur = dn;
        }
        __syncthreads();
    }

    // ---- write valid center TX x TX (final state in b0 since K is even) ----
    for (int y = K + warp; y <= BW - 1 - K; y += 16) {
        int gy = gy0 + y;
        if (gy >= N) break;
        for (int x = K + lane; x <= BW - 1 - K; x += 32) {
            int gx = gx0 + x;
            if (gx < N)
                out[(size_t)gy * N + gx] = b0[y * BW + x];
        }
    }
}

extern "C" void kernel_launch(void* const* d_in, const int* in_sizes, int n_in,
                              void* d_out, int out_size) {
    const float* X = (const float*)d_in[0];
    const float* Y = (const float*)d_in[1];
    float* A = (float*)d_out;
    float* B;
    cudaGetSymbolAddress((void**)&B, g_buf);

    const int smem_bytes = 2 * BW * BW * (int)sizeof(float);   // 131072
    cudaFuncSetAttribute(jacobi_pass,
                         cudaFuncAttributeMaxDynamicSharedMemorySize, smem_bytes);

    // init: x0 -> A
    init_kernel<<<(N * N) / 256, 256>>>(X, Y, A);

    // 10 passes of K=10 fused steps each; 10 even -> final lands in A (=d_out)
    dim3 grid(NBLK, NBLK);
    for (int p = 0; p < 100 / K; p++) {
        const float* src = (p % 2 == 0) ? A : B;
        float*       dst = (p % 2 == 0) ? B : A;
        jacobi_pass<<<grid, NTH, smem_bytes>>>(src, dst);
    }
}